// round 2
// baseline (speedup 1.0000x reference)
#include <cuda_runtime.h>
#include <cuda_bf16.h>

// Problem constants
#define B_SZ   4096
#define HH     128
#define PHI_D  784
#define H1_D   128
#define H2_D   256
#define WIN    112
#define WSTRIDE 113
#define EPS    1e-5f
#define NSPLIT 4
#define SPLIT_OFF (B_SZ * H1_D)

// ---------------- scratch ----------------------------------------------------
__device__ float g_phi[B_SZ * PHI_D];
__device__ float g_h1p[NSPLIT * B_SZ * H1_D];   // split-K partials
__device__ float g_h1 [B_SZ * H1_D];
__device__ float g_h2 [B_SZ * H2_D];
__device__ float g_h2w[B_SZ * H2_D];
__device__ float g_sum1[2 * H1_D];
__device__ float g_sq1 [2 * H1_D];
__device__ float g_sc1 [2 * H1_D];
__device__ float g_sh1 [2 * H1_D];
__device__ float g_sum2[2 * H2_D];
__device__ float g_sq2 [2 * H2_D];
__device__ float g_sc2 [2 * H2_D];
__device__ float g_sh2 [2 * H2_D];

// ---------------- K0: zero stat accumulators --------------------------------
__global__ void zero_stats_kernel() {
    int i = threadIdx.x;                       // 512 threads
    if (i < 256) { g_sum1[i] = 0.f; g_sq1[i] = 0.f; }
    g_sum2[i] = 0.f; g_sq2[i] = 0.f;
}

// ---------------- K1: foveate -> phi (4096 x 784) ----------------------------
__global__ void foveate_kernel(const float* __restrict__ x,
                               const float* __restrict__ loc,
                               float* __restrict__ phi) {
    extern __shared__ float win[];             // WIN * WSTRIDE
    int b = blockIdx.x;
    float lx = loc[2 * b + 0];
    float ly = loc[2 * b + 1];
    int cx = (int)(0.5f * ((lx + 1.0f) * 128.0f));
    int cy = (int)(0.5f * ((ly + 1.0f) * 128.0f));
    int wy0 = cy - 56, wx0 = cx - 56;
    const float* xb = x + (size_t)b * HH * HH;

    // 512 threads: c = tid&127 (only <112 active), r strided by 4
    int c  = threadIdx.x & 127;
    int r0 = threadIdx.x >> 7;
    if (c < WIN) {
        int gx = wx0 + c;
        bool xok = (gx >= 0 && gx < HH);
        for (int r = r0; r < WIN; r += 4) {
            int gy = wy0 + r;
            float v = 0.f;
            if (xok && gy >= 0 && gy < HH) v = xb[gy * HH + gx];
            win[r * WSTRIDE + c] = v;
        }
    }
    __syncthreads();

    for (int o = threadIdx.x; o < PHI_D; o += blockDim.x) {
        int p   = o / 196;
        int rem = o - p * 196;
        int i   = rem / 14;
        int j   = rem - i * 14;
        int k   = 1 << p;                      // 1,2,4,8
        int off = 56 - 7 * k;
        int rb  = off + i * k;
        int cb  = off + j * k;
        float s = 0.f;
        for (int di = 0; di < k; di++) {
            const float* row = &win[(rb + di) * WSTRIDE + cb];
            for (int dj = 0; dj < k; dj++) s += row[dj];
        }
        phi[(size_t)b * PHI_D + o] = s * (1.0f / (float)(k * k));
    }
}

// ---------------- K2: GEMM1 split-K: h1p[s] = phi @ W1 (K chunk s) -----------
// BM=64, BN=64, BK=16, 256 threads, 4x4 micro-tile, 4 K-splits.
__global__ void gemm1_kernel(const float* __restrict__ A,   // (4096,784)
                             const float* __restrict__ W) { // (784,128)
    __shared__ float As[16][68];
    __shared__ float Bs[16][68];
    int s = blockIdx.z;
    int t0 = (s == 0) ? 0 : 13 + 12 * (s - 1);   // tiles of 16: [0,13,25,37]
    int t1 = t0 + ((s == 0) ? 13 : 12);
    float* out = g_h1p + (size_t)s * SPLIT_OFF;

    int t = threadIdx.x;
    int rowBase = blockIdx.x * 64;
    int colBase = blockIdx.y * 64;
    int ty = t >> 4, tx = t & 15;
    float acc[4][4] = {};

    int lc = t & 15;
    int lr = (t >> 4) << 2;
    int bc = t & 63;
    int br = t >> 6;

    for (int kt = t0; kt < t1; kt++) {
        int k0 = kt * 16;
        #pragma unroll
        for (int rr = 0; rr < 4; rr++)
            As[lc][lr + rr] = A[(size_t)(rowBase + lr + rr) * PHI_D + k0 + lc];
        #pragma unroll
        for (int pp = 0; pp < 4; pp++)
            Bs[br * 4 + pp][bc] = W[(size_t)(k0 + br * 4 + pp) * H1_D + colBase + bc];
        __syncthreads();
        #pragma unroll
        for (int kk = 0; kk < 16; kk++) {
            float4 a = *(const float4*)&As[kk][ty * 4];
            float4 b = *(const float4*)&Bs[kk][tx * 4];
            acc[0][0] += a.x * b.x; acc[0][1] += a.x * b.y; acc[0][2] += a.x * b.z; acc[0][3] += a.x * b.w;
            acc[1][0] += a.y * b.x; acc[1][1] += a.y * b.y; acc[1][2] += a.y * b.z; acc[1][3] += a.y * b.w;
            acc[2][0] += a.z * b.x; acc[2][1] += a.z * b.y; acc[2][2] += a.z * b.z; acc[2][3] += a.z * b.w;
            acc[3][0] += a.w * b.x; acc[3][1] += a.w * b.y; acc[3][2] += a.w * b.z; acc[3][3] += a.w * b.w;
        }
        __syncthreads();
    }
    #pragma unroll
    for (int rr = 0; rr < 4; rr++) {
        int row = rowBase + ty * 4 + rr;
        #pragma unroll
        for (int cc = 0; cc < 4; cc++)
            out[(size_t)row * H1_D + colBase + tx * 4 + cc] = acc[rr][cc];
    }
}

// ---------------- K3: reduce partials -> g_h1, column stats (both paths) -----
__global__ void stats1_kernel(const float* __restrict__ loc,
                              const float* __restrict__ Ww1) {
    int t = threadIdx.x;               // 256
    int base = blockIdx.x * 128;       // 32 blocks x 128 rows
    int col = t & 127;
    if (t < 128) {
        float s = 0.f, q = 0.f;
        for (int r = 0; r < 128; r++) {
            int idx = (base + r) * H1_D + col;
            float v = g_h1p[idx] + g_h1p[idx + SPLIT_OFF]
                    + g_h1p[idx + 2 * SPLIT_OFF] + g_h1p[idx + 3 * SPLIT_OFF];
            g_h1[idx] = v;
            s += v; q += v * v;
        }
        atomicAdd(&g_sum1[col], s); atomicAdd(&g_sq1[col], q);
    } else {
        float w0 = Ww1[col], w1 = Ww1[H1_D + col];
        float s = 0.f, q = 0.f;
        for (int r = 0; r < 128; r++) {
            int b = base + r;
            float v = loc[2 * b] * w0 + loc[2 * b + 1] * w1;
            s += v; q += v * v;
        }
        atomicAdd(&g_sum1[128 + col], s); atomicAdd(&g_sq1[128 + col], q);
    }
}

__global__ void finalize1_kernel(const float* __restrict__ g1, const float* __restrict__ be1,
                                 const float* __restrict__ gw1, const float* __restrict__ bew1) {
    int j = threadIdx.x;               // 256
    float mean = g_sum1[j] * (1.0f / 4096.0f);
    float var  = g_sq1[j] * (1.0f / 4096.0f) - mean * mean;
    float g  = (j < 128) ? g1[j]  : gw1[j - 128];
    float be = (j < 128) ? be1[j] : bew1[j - 128];
    float sc = g * rsqrtf(var + EPS);
    g_sc1[j] = sc;
    g_sh1[j] = be - mean * sc;
}

// ---------------- K4: GEMM2 (both paths), BN+relu fused on A -----------------
// Path 1 recomputes h1w = loc @ Ww1 on the fly (rank-2, loc hoisted per-thread).
__global__ void gemm2_kernel(const float* __restrict__ W2,     // (128,256)
                             const float* __restrict__ Ww2,    // (128,256)
                             const float* __restrict__ loc,
                             const float* __restrict__ Ww1) {  // (2,128)
    __shared__ float As[16][68];
    __shared__ float Bs[16][68];
    int path = blockIdx.z;
    const float* W   = path ? Ww2   : W2;
    float*       out = path ? g_h2w : g_h2;
    const float* sc = g_sc1 + path * H1_D;
    const float* sh = g_sh1 + path * H1_D;

    int t = threadIdx.x;
    int rowBase = blockIdx.x * 64;
    int colBase = blockIdx.y * 64;
    int ty = t >> 4, tx = t & 15;
    float acc[4][4] = {};

    int lc = t & 15;
    int lr = (t >> 4) << 2;
    int bc = t & 63;
    int br = t >> 6;

    // loc values for the 4 rows this thread loads (constant across K)
    float lxv[4], lyv[4];
    if (path) {
        #pragma unroll
        for (int rr = 0; rr < 4; rr++) {
            int row = rowBase + lr + rr;
            lxv[rr] = loc[2 * row];
            lyv[rr] = loc[2 * row + 1];
        }
    }

    for (int k0 = 0; k0 < H1_D; k0 += 16) {
        int kc = k0 + lc;
        float s = sc[kc], h = sh[kc];
        if (path == 0) {
            #pragma unroll
            for (int rr = 0; rr < 4; rr++) {
                float v = g_h1[(size_t)(rowBase + lr + rr) * H1_D + kc];
                As[lc][lr + rr] = fmaxf(v * s + h, 0.f);
            }
        } else {
            float w0 = Ww1[kc], w1 = Ww1[H1_D + kc];
            #pragma unroll
            for (int rr = 0; rr < 4; rr++) {
                float v = lxv[rr] * w0 + lyv[rr] * w1;
                As[lc][lr + rr] = fmaxf(v * s + h, 0.f);
            }
        }
        #pragma unroll
        for (int pp = 0; pp < 4; pp++)
            Bs[br * 4 + pp][bc] = W[(size_t)(k0 + br * 4 + pp) * H2_D + colBase + bc];
        __syncthreads();
        #pragma unroll
        for (int kk = 0; kk < 16; kk++) {
            float4 a = *(const float4*)&As[kk][ty * 4];
            float4 b = *(const float4*)&Bs[kk][tx * 4];
            acc[0][0] += a.x * b.x; acc[0][1] += a.x * b.y; acc[0][2] += a.x * b.z; acc[0][3] += a.x * b.w;
            acc[1][0] += a.y * b.x; acc[1][1] += a.y * b.y; acc[1][2] += a.y * b.z; acc[1][3] += a.y * b.w;
            acc[2][0] += a.z * b.x; acc[2][1] += a.z * b.y; acc[2][2] += a.z * b.z; acc[2][3] += a.z * b.w;
            acc[3][0] += a.w * b.x; acc[3][1] += a.w * b.y; acc[3][2] += a.w * b.z; acc[3][3] += a.w * b.w;
        }
        __syncthreads();
    }
    #pragma unroll
    for (int rr = 0; rr < 4; rr++) {
        int row = rowBase + ty * 4 + rr;
        #pragma unroll
        for (int cc = 0; cc < 4; cc++)
            out[(size_t)row * H2_D + colBase + tx * 4 + cc] = acc[rr][cc];
    }
}

// ---------------- K5: column stats of h2 / h2w ------------------------------
__global__ void stats2_kernel() {
    int t = threadIdx.x;               // 256
    int base = blockIdx.x * 128;       // 32 blocks x 128 rows
    float s1 = 0, q1 = 0, s2 = 0, q2 = 0;
    for (int it = 0; it < 128; it++) {
        int idx = (base + it) * H2_D + t;
        float v = g_h2[idx];  s1 += v; q1 += v * v;
        float w = g_h2w[idx]; s2 += w; q2 += w * w;
    }
    atomicAdd(&g_sum2[t], s1);        atomicAdd(&g_sq2[t], q1);
    atomicAdd(&g_sum2[256 + t], s2);  atomicAdd(&g_sq2[256 + t], q2);
}

__global__ void finalize2_kernel(const float* __restrict__ g2, const float* __restrict__ be2,
                                 const float* __restrict__ gw2, const float* __restrict__ bew2) {
    int j = threadIdx.x;               // 512
    float mean = g_sum2[j] * (1.0f / 4096.0f);
    float var  = g_sq2[j] * (1.0f / 4096.0f) - mean * mean;
    float g  = (j < 256) ? g2[j]  : gw2[j - 256];
    float be = (j < 256) ? be2[j] : bew2[j - 256];
    float sc = g * rsqrtf(var + EPS);
    g_sc2[j] = sc;
    g_sh2[j] = be - mean * sc;
}

// ---------------- K6: out = relu(BN(h2) + BN(h2w)) ---------------------------
__global__ void final_kernel(float* __restrict__ out) {
    int idx = blockIdx.x * blockDim.x + threadIdx.x;   // 1048576
    int c = idx & 255;
    float a = g_h2[idx]  * g_sc2[c]       + g_sh2[c];
    float b = g_h2w[idx] * g_sc2[256 + c] + g_sh2[256 + c];
    out[idx] = fmaxf(a + b, 0.f);
}

// ---------------- launch -----------------------------------------------------
extern "C" void kernel_launch(void* const* d_in, const int* in_sizes, int n_in,
                              void* d_out, int out_size) {
    const float* x        = (const float*)d_in[0];
    const float* loc      = (const float*)d_in[1];
    const float* what_W1  = (const float*)d_in[2];
    const float* what_g1  = (const float*)d_in[4];
    const float* what_be1 = (const float*)d_in[5];
    const float* what_W2  = (const float*)d_in[6];
    const float* what_g2  = (const float*)d_in[8];
    const float* what_be2 = (const float*)d_in[9];
    const float* where_W1  = (const float*)d_in[10];
    const float* where_g1  = (const float*)d_in[12];
    const float* where_be1 = (const float*)d_in[13];
    const float* where_W2  = (const float*)d_in[14];
    const float* where_g2  = (const float*)d_in[16];
    const float* where_be2 = (const float*)d_in[17];
    float* out = (float*)d_out;

    static float* p_phi = nullptr;
    if (!p_phi) {
        cudaGetSymbolAddress((void**)&p_phi, g_phi);
        const int FOV_SMEM = WIN * WSTRIDE * sizeof(float);
        cudaFuncSetAttribute(foveate_kernel,
                             cudaFuncAttributeMaxDynamicSharedMemorySize, FOV_SMEM);
    }
    const int FOV_SMEM = WIN * WSTRIDE * sizeof(float);   // 50624 B

    zero_stats_kernel<<<1, 512>>>();
    foveate_kernel<<<B_SZ, 512, FOV_SMEM>>>(x, loc, p_phi);
    gemm1_kernel<<<dim3(B_SZ / 64, H1_D / 64, NSPLIT), 256>>>(p_phi, what_W1);
    stats1_kernel<<<32, 256>>>(loc, where_W1);
    finalize1_kernel<<<1, 256>>>(what_g1, what_be1, where_g1, where_be1);
    gemm2_kernel<<<dim3(B_SZ / 64, H2_D / 64, 2), 256>>>(what_W2, where_W2, loc, where_W1);
    stats2_kernel<<<32, 256>>>();
    finalize2_kernel<<<1, 512>>>(what_g2, what_be2, where_g2, where_be2);
    final_kernel<<<(B_SZ * H2_D) / 512, 512>>>(out);
}

// round 3
// speedup vs baseline: 1.2664x; 1.2664x over previous
#include <cuda_runtime.h>
#include <cuda_bf16.h>

// Problem constants
#define B_SZ   4096
#define HH     128
#define PHI_D  784
#define H1_D   128
#define H2_D   256
#define WIN    112
#define WSTRIDE 113
#define EPS    1e-5f
#define NSPLIT 4
#define SPLIT_OFF (B_SZ * H1_D)

// ---------------- scratch ----------------------------------------------------
__device__ float g_phi[B_SZ * PHI_D];
__device__ float g_h1p[NSPLIT * B_SZ * H1_D];   // split-K partials
__device__ float g_h1 [B_SZ * H1_D];
__device__ float g_h2 [B_SZ * H2_D];
__device__ float g_h2w[B_SZ * H2_D];
__device__ float g_sum1[2 * H1_D];
__device__ float g_sq1 [2 * H1_D];
__device__ float g_sum2[2 * H2_D];
__device__ float g_sq2 [2 * H2_D];

// ---------------- K1: foveate -> phi (4096 x 784); block0 zeroes sum1 --------
__global__ void foveate_kernel(const float* __restrict__ x,
                               const float* __restrict__ loc,
                               float* __restrict__ phi) {
    extern __shared__ float win[];             // WIN * WSTRIDE
    int b = blockIdx.x;
    if (b == 0 && threadIdx.x < 256) {         // zero layer-1 stat accumulators
        g_sum1[threadIdx.x] = 0.f;
        g_sq1[threadIdx.x] = 0.f;
    }
    float lx = loc[2 * b + 0];
    float ly = loc[2 * b + 1];
    int cx = (int)(0.5f * ((lx + 1.0f) * 128.0f));
    int cy = (int)(0.5f * ((ly + 1.0f) * 128.0f));
    int wy0 = cy - 56, wx0 = cx - 56;
    const float* xb = x + (size_t)b * HH * HH;

    int c  = threadIdx.x & 127;
    int r0 = threadIdx.x >> 7;
    if (c < WIN) {
        int gx = wx0 + c;
        bool xok = (gx >= 0 && gx < HH);
        for (int r = r0; r < WIN; r += 4) {
            int gy = wy0 + r;
            float v = 0.f;
            if (xok && gy >= 0 && gy < HH) v = xb[gy * HH + gx];
            win[r * WSTRIDE + c] = v;
        }
    }
    __syncthreads();

    for (int o = threadIdx.x; o < PHI_D; o += blockDim.x) {
        int p   = o / 196;
        int rem = o - p * 196;
        int i   = rem / 14;
        int j   = rem - i * 14;
        int k   = 1 << p;                      // 1,2,4,8
        int off = 56 - 7 * k;
        int rb  = off + i * k;
        int cb  = off + j * k;
        float s = 0.f;
        for (int di = 0; di < k; di++) {
            const float* row = &win[(rb + di) * WSTRIDE + cb];
            for (int dj = 0; dj < k; dj++) s += row[dj];
        }
        phi[(size_t)b * PHI_D + o] = s * (1.0f / (float)(k * k));
    }
}

// ---------------- K2: GEMM1 split-K: h1p[s] = phi @ W1 (K chunk s) -----------
__global__ void gemm1_kernel(const float* __restrict__ A,   // (4096,784)
                             const float* __restrict__ W) { // (784,128)
    __shared__ float As[16][68];
    __shared__ float Bs[16][68];
    int s = blockIdx.z;
    int t0 = (s == 0) ? 0 : 13 + 12 * (s - 1);   // tiles of 16: [0,13,25,37]
    int t1 = t0 + ((s == 0) ? 13 : 12);
    float* out = g_h1p + (size_t)s * SPLIT_OFF;

    int t = threadIdx.x;
    int rowBase = blockIdx.x * 64;
    int colBase = blockIdx.y * 64;
    int ty = t >> 4, tx = t & 15;
    float acc[4][4] = {};

    int lc = t & 15;
    int lr = (t >> 4) << 2;
    int bc = t & 63;
    int br = t >> 6;

    for (int kt = t0; kt < t1; kt++) {
        int k0 = kt * 16;
        #pragma unroll
        for (int rr = 0; rr < 4; rr++)
            As[lc][lr + rr] = A[(size_t)(rowBase + lr + rr) * PHI_D + k0 + lc];
        #pragma unroll
        for (int pp = 0; pp < 4; pp++)
            Bs[br * 4 + pp][bc] = W[(size_t)(k0 + br * 4 + pp) * H1_D + colBase + bc];
        __syncthreads();
        #pragma unroll
        for (int kk = 0; kk < 16; kk++) {
            float4 a = *(const float4*)&As[kk][ty * 4];
            float4 b = *(const float4*)&Bs[kk][tx * 4];
            acc[0][0] += a.x * b.x; acc[0][1] += a.x * b.y; acc[0][2] += a.x * b.z; acc[0][3] += a.x * b.w;
            acc[1][0] += a.y * b.x; acc[1][1] += a.y * b.y; acc[1][2] += a.y * b.z; acc[1][3] += a.y * b.w;
            acc[2][0] += a.z * b.x; acc[2][1] += a.z * b.y; acc[2][2] += a.z * b.z; acc[2][3] += a.z * b.w;
            acc[3][0] += a.w * b.x; acc[3][1] += a.w * b.y; acc[3][2] += a.w * b.z; acc[3][3] += a.w * b.w;
        }
        __syncthreads();
    }
    #pragma unroll
    for (int rr = 0; rr < 4; rr++) {
        int row = rowBase + ty * 4 + rr;
        #pragma unroll
        for (int cc = 0; cc < 4; cc++)
            out[(size_t)row * H1_D + colBase + tx * 4 + cc] = acc[rr][cc];
    }
}

// ---------------- K3: reduce partials -> g_h1 + column stats (both paths) ----
// grid 256 x block 256. 16 rows per block, 2 rows per iteration.
__global__ void stats1_kernel(const float* __restrict__ loc,
                              const float* __restrict__ Ww1) {
    int t = threadIdx.x;
    int row0 = blockIdx.x * 16;
    int col = t & 127;
    int rh = t >> 7;                   // 0 or 1

    if (blockIdx.x == 0 && t < 256) {  // zero layer-2 stat accumulators
        g_sum2[t] = 0.f; g_sum2[t + 256] = 0.f;
        g_sq2[t] = 0.f;  g_sq2[t + 256] = 0.f;
    }

    float s = 0.f, q = 0.f;
    #pragma unroll
    for (int r = 0; r < 16; r += 2) {
        int idx = (row0 + r + rh) * H1_D + col;
        float v = g_h1p[idx] + g_h1p[idx + SPLIT_OFF]
                + g_h1p[idx + 2 * SPLIT_OFF] + g_h1p[idx + 3 * SPLIT_OFF];
        g_h1[idx] = v;
        s += v; q += v * v;
    }
    atomicAdd(&g_sum1[col], s); atomicAdd(&g_sq1[col], q);

    // where path: recompute h1w = loc @ Ww1 (rank-2)
    float w0 = Ww1[col], w1 = Ww1[H1_D + col];
    s = 0.f; q = 0.f;
    #pragma unroll
    for (int r = 0; r < 16; r += 2) {
        int b = row0 + r + rh;
        float v = loc[2 * b] * w0 + loc[2 * b + 1] * w1;
        s += v; q += v * v;
    }
    atomicAdd(&g_sum1[H1_D + col], s); atomicAdd(&g_sq1[H1_D + col], q);
}

// ---------------- K4: GEMM2 (both paths); BN params computed inline ----------
__global__ void gemm2_kernel(const float* __restrict__ W2,     // (128,256)
                             const float* __restrict__ Ww2,    // (128,256)
                             const float* __restrict__ loc,
                             const float* __restrict__ Ww1,    // (2,128)
                             const float* __restrict__ g1, const float* __restrict__ be1,
                             const float* __restrict__ gw1, const float* __restrict__ bew1) {
    __shared__ float As[16][68];
    __shared__ float Bs[16][68];
    int path = blockIdx.z;
    const float* W   = path ? Ww2   : W2;
    float*       out = path ? g_h2w : g_h2;
    const float* gam = path ? gw1 : g1;
    const float* bet = path ? bew1 : be1;
    int soff = path * H1_D;

    int t = threadIdx.x;
    int rowBase = blockIdx.x * 64;
    int colBase = blockIdx.y * 64;
    int ty = t >> 4, tx = t & 15;
    float acc[4][4] = {};

    int lc = t & 15;
    int lr = (t >> 4) << 2;
    int bc = t & 63;
    int br = t >> 6;

    float lxv[4], lyv[4];
    if (path) {
        #pragma unroll
        for (int rr = 0; rr < 4; rr++) {
            int row = rowBase + lr + rr;
            lxv[rr] = loc[2 * row];
            lyv[rr] = loc[2 * row + 1];
        }
    }

    for (int k0 = 0; k0 < H1_D; k0 += 16) {
        int kc = k0 + lc;
        // inline BN finalize for column kc of this path
        float mean = g_sum1[soff + kc] * (1.0f / 4096.0f);
        float var  = g_sq1[soff + kc] * (1.0f / 4096.0f) - mean * mean;
        float s = gam[kc] * rsqrtf(var + EPS);
        float h = bet[kc] - mean * s;
        if (path == 0) {
            #pragma unroll
            for (int rr = 0; rr < 4; rr++) {
                float v = g_h1[(size_t)(rowBase + lr + rr) * H1_D + kc];
                As[lc][lr + rr] = fmaxf(v * s + h, 0.f);
            }
        } else {
            float w0 = Ww1[kc], w1 = Ww1[H1_D + kc];
            #pragma unroll
            for (int rr = 0; rr < 4; rr++) {
                float v = lxv[rr] * w0 + lyv[rr] * w1;
                As[lc][lr + rr] = fmaxf(v * s + h, 0.f);
            }
        }
        #pragma unroll
        for (int pp = 0; pp < 4; pp++)
            Bs[br * 4 + pp][bc] = W[(size_t)(k0 + br * 4 + pp) * H2_D + colBase + bc];
        __syncthreads();
        #pragma unroll
        for (int kk = 0; kk < 16; kk++) {
            float4 a = *(const float4*)&As[kk][ty * 4];
            float4 b = *(const float4*)&Bs[kk][tx * 4];
            acc[0][0] += a.x * b.x; acc[0][1] += a.x * b.y; acc[0][2] += a.x * b.z; acc[0][3] += a.x * b.w;
            acc[1][0] += a.y * b.x; acc[1][1] += a.y * b.y; acc[1][2] += a.y * b.z; acc[1][3] += a.y * b.w;
            acc[2][0] += a.z * b.x; acc[2][1] += a.z * b.y; acc[2][2] += a.z * b.z; acc[2][3] += a.z * b.w;
            acc[3][0] += a.w * b.x; acc[3][1] += a.w * b.y; acc[3][2] += a.w * b.z; acc[3][3] += a.w * b.w;
        }
        __syncthreads();
    }
    #pragma unroll
    for (int rr = 0; rr < 4; rr++) {
        int row = rowBase + ty * 4 + rr;
        #pragma unroll
        for (int cc = 0; cc < 4; cc++)
            out[(size_t)row * H2_D + colBase + tx * 4 + cc] = acc[rr][cc];
    }
}

// ---------------- K5: column stats of h2 / h2w: grid 256 ---------------------
__global__ void stats2_kernel() {
    int t = threadIdx.x;               // 256
    int row0 = blockIdx.x * 16;        // 256 blocks x 16 rows
    float s1 = 0, q1 = 0, s2 = 0, q2 = 0;
    #pragma unroll
    for (int r = 0; r < 16; r++) {
        int idx = (row0 + r) * H2_D + t;
        float v = g_h2[idx];  s1 += v; q1 += v * v;
        float w = g_h2w[idx]; s2 += w; q2 += w * w;
    }
    atomicAdd(&g_sum2[t], s1);        atomicAdd(&g_sq2[t], q1);
    atomicAdd(&g_sum2[256 + t], s2);  atomicAdd(&g_sq2[256 + t], q2);
}

// ---------------- K6: out = relu(BN(h2) + BN(h2w)), finalize inline ----------
__global__ void final_kernel(const float* __restrict__ g2, const float* __restrict__ be2,
                             const float* __restrict__ gw2, const float* __restrict__ bew2,
                             float* __restrict__ out) {
    int idx = blockIdx.x * blockDim.x + threadIdx.x;   // 1048576
    int c = idx & 255;
    float m0 = g_sum2[c] * (1.0f / 4096.0f);
    float v0 = g_sq2[c] * (1.0f / 4096.0f) - m0 * m0;
    float s0 = g2[c] * rsqrtf(v0 + EPS);
    float h0 = be2[c] - m0 * s0;
    float m1 = g_sum2[256 + c] * (1.0f / 4096.0f);
    float v1 = g_sq2[256 + c] * (1.0f / 4096.0f) - m1 * m1;
    float s1 = gw2[c] * rsqrtf(v1 + EPS);
    float h1 = bew2[c] - m1 * s1;
    float a = g_h2[idx]  * s0 + h0;
    float b = g_h2w[idx] * s1 + h1;
    out[idx] = fmaxf(a + b, 0.f);
}

// ---------------- launch -----------------------------------------------------
extern "C" void kernel_launch(void* const* d_in, const int* in_sizes, int n_in,
                              void* d_out, int out_size) {
    const float* x        = (const float*)d_in[0];
    const float* loc      = (const float*)d_in[1];
    const float* what_W1  = (const float*)d_in[2];
    const float* what_g1  = (const float*)d_in[4];
    const float* what_be1 = (const float*)d_in[5];
    const float* what_W2  = (const float*)d_in[6];
    const float* what_g2  = (const float*)d_in[8];
    const float* what_be2 = (const float*)d_in[9];
    const float* where_W1  = (const float*)d_in[10];
    const float* where_g1  = (const float*)d_in[12];
    const float* where_be1 = (const float*)d_in[13];
    const float* where_W2  = (const float*)d_in[14];
    const float* where_g2  = (const float*)d_in[16];
    const float* where_be2 = (const float*)d_in[17];
    float* out = (float*)d_out;

    static float* p_phi = nullptr;
    if (!p_phi) {
        cudaGetSymbolAddress((void**)&p_phi, g_phi);
        const int FOV_SMEM = WIN * WSTRIDE * sizeof(float);
        cudaFuncSetAttribute(foveate_kernel,
                             cudaFuncAttributeMaxDynamicSharedMemorySize, FOV_SMEM);
    }
    const int FOV_SMEM = WIN * WSTRIDE * sizeof(float);   // 50624 B

    foveate_kernel<<<B_SZ, 512, FOV_SMEM>>>(x, loc, p_phi);
    gemm1_kernel<<<dim3(B_SZ / 64, H1_D / 64, NSPLIT), 256>>>(p_phi, what_W1);
    stats1_kernel<<<256, 256>>>(loc, where_W1);
    gemm2_kernel<<<dim3(B_SZ / 64, H2_D / 64, 2), 256>>>(
        what_W2, where_W2, loc, where_W1,
        what_g1, what_be1, where_g1, where_be1);
    stats2_kernel<<<256, 256>>>();
    final_kernel<<<(B_SZ * H2_D) / 512, 512>>>(
        what_g2, what_be2, where_g2, where_be2, out);
}

// round 5
// speedup vs baseline: 1.5499x; 1.2239x over previous
#include <cuda_runtime.h>
#include <cuda_bf16.h>

// Problem constants
#define B_SZ   4096
#define HH     128
#define PHI_D  784
#define H1_D   128
#define H2_D   256
#define WIN    112
#define WSTRIDE 113
#define L1W    57
#define L2W    29
#define EPS    1e-5f
#define NSPLIT 8
#define SPLIT_OFF (B_SZ * H1_D)

// ---------------- scratch ----------------------------------------------------
__device__ float g_phi[B_SZ * PHI_D];
__device__ float g_h1p[NSPLIT * B_SZ * H1_D];   // split-K partials
__device__ float g_h1 [B_SZ * H1_D];
__device__ float g_h2 [B_SZ * H2_D];
__device__ float g_h2w[B_SZ * H2_D];
__device__ float g_sum1[2 * H1_D];
__device__ float g_sq1 [2 * H1_D];
__device__ float g_sum2[2 * H2_D];
__device__ float g_sq2 [2 * H2_D];

// ---------------- K1: foveate -> phi via 2-level sum pyramid -----------------
// Patch p: size 14*2^p, window top-left 56-7*2^p: p0->49, p1->42, p2->28, p3->0
__global__ void foveate_kernel(const float* __restrict__ x,
                               const float* __restrict__ loc,
                               float* __restrict__ phi) {
    extern __shared__ float smem[];
    float* win = smem;                          // 112 x 113
    float* L1  = smem + WIN * WSTRIDE;          // 56 x 57 (2x2 sums of win)
    float* L2  = L1 + 56 * L1W;                 // 28 x 29 (2x2 sums of L1)

    int b = blockIdx.x;
    if (b == 0 && threadIdx.x < 256) {          // zero layer-1 stat accumulators
        g_sum1[threadIdx.x] = 0.f;
        g_sq1[threadIdx.x] = 0.f;
    }
    float lx = loc[2 * b + 0];
    float ly = loc[2 * b + 1];
    int cx = (int)(0.5f * ((lx + 1.0f) * 128.0f));
    int cy = (int)(0.5f * ((ly + 1.0f) * 128.0f));
    int wy0 = cy - 56, wx0 = cx - 56;
    const float* xb = x + (size_t)b * HH * HH;

    // Load 112x112 window (zero padded)
    int c  = threadIdx.x & 127;
    int r0 = threadIdx.x >> 7;
    if (c < WIN) {
        int gx = wx0 + c;
        bool xok = (gx >= 0 && gx < HH);
        for (int r = r0; r < WIN; r += 4) {
            int gy = wy0 + r;
            float v = 0.f;
            if (xok && gy >= 0 && gy < HH) v = xb[gy * HH + gx];
            win[r * WSTRIDE + c] = v;
        }
    }
    __syncthreads();

    // L1: 2x2 sums -> 56x56
    for (int i = threadIdx.x; i < 56 * 56; i += 512) {
        int r = i / 56, cc = i - r * 56;
        const float* w0 = &win[(2 * r) * WSTRIDE + 2 * cc];
        const float* w1 = w0 + WSTRIDE;
        L1[r * L1W + cc] = (w0[0] + w0[1]) + (w1[0] + w1[1]);
    }
    __syncthreads();

    // L2: 2x2 sums of L1 -> 28x28
    for (int i = threadIdx.x; i < 28 * 28; i += 512) {
        int r = i / 28, cc = i - r * 28;
        const float* a0 = &L1[(2 * r) * L1W + 2 * cc];
        const float* a1 = a0 + L1W;
        L2[r * L2W + cc] = (a0[0] + a0[1]) + (a1[0] + a1[1]);
    }
    __syncthreads();

    // Outputs: 784 = 4 patches x 14 x 14
    for (int o = threadIdx.x; o < PHI_D; o += 512) {
        int p   = o / 196;
        int rem = o - p * 196;
        int i   = rem / 14;
        int j   = rem - i * 14;
        float v;
        if (p == 0) {
            v = win[(49 + i) * WSTRIDE + 49 + j];          // offset 49, no pooling
        } else if (p == 1) {
            v = L1[(21 + i) * L1W + 21 + j] * 0.25f;       // offset 42 -> L1 21
        } else if (p == 2) {
            v = L2[(7 + i) * L2W + 7 + j] * 0.0625f;       // offset 28 -> L2 7
        } else {
            const float* q0 = &L2[(2 * i) * L2W + 2 * j];  // offset 0, 8x8 pool
            const float* q1 = q0 + L2W;
            v = ((q0[0] + q0[1]) + (q1[0] + q1[1])) * (1.0f / 64.0f);
        }
        phi[(size_t)b * PHI_D + o] = v;
    }
}

// ---------------- K2: GEMM1 split-K (8 splits): h1p[s] = phi @ W1 ------------
__global__ void gemm1_kernel(const float* __restrict__ A,   // (4096,784)
                             const float* __restrict__ W) { // (784,128)
    __shared__ float As[16][68];
    __shared__ float Bs[16][68];
    int s = blockIdx.z;
    int t0 = (s == 0) ? 0 : 7 + 6 * (s - 1);    // 49 tiles: [7,6,6,6,6,6,6,6]
    int t1 = t0 + ((s == 0) ? 7 : 6);
    float* out = g_h1p + (size_t)s * SPLIT_OFF;

    int t = threadIdx.x;
    int rowBase = blockIdx.x * 64;
    int colBase = blockIdx.y * 64;
    int ty = t >> 4, tx = t & 15;
    float acc[4][4] = {};

    int lc = t & 15;
    int lr = (t >> 4) << 2;
    int bc = t & 63;
    int br = t >> 6;

    for (int kt = t0; kt < t1; kt++) {
        int k0 = kt * 16;
        #pragma unroll
        for (int rr = 0; rr < 4; rr++)
            As[lc][lr + rr] = A[(size_t)(rowBase + lr + rr) * PHI_D + k0 + lc];
        #pragma unroll
        for (int pp = 0; pp < 4; pp++)
            Bs[br * 4 + pp][bc] = W[(size_t)(k0 + br * 4 + pp) * H1_D + colBase + bc];
        __syncthreads();
        #pragma unroll
        for (int kk = 0; kk < 16; kk++) {
            float4 a = *(const float4*)&As[kk][ty * 4];
            float4 b = *(const float4*)&Bs[kk][tx * 4];
            acc[0][0] += a.x * b.x; acc[0][1] += a.x * b.y; acc[0][2] += a.x * b.z; acc[0][3] += a.x * b.w;
            acc[1][0] += a.y * b.x; acc[1][1] += a.y * b.y; acc[1][2] += a.y * b.z; acc[1][3] += a.y * b.w;
            acc[2][0] += a.z * b.x; acc[2][1] += a.z * b.y; acc[2][2] += a.z * b.z; acc[2][3] += a.z * b.w;
            acc[3][0] += a.w * b.x; acc[3][1] += a.w * b.y; acc[3][2] += a.w * b.z; acc[3][3] += a.w * b.w;
        }
        __syncthreads();
    }
    #pragma unroll
    for (int rr = 0; rr < 4; rr++) {
        int row = rowBase + ty * 4 + rr;
        #pragma unroll
        for (int cc = 0; cc < 4; cc++)
            out[(size_t)row * H1_D + colBase + tx * 4 + cc] = acc[rr][cc];
    }
}

// ---------------- K3: reduce partials -> g_h1 + column stats (both paths) ----
__global__ void stats1_kernel(const float* __restrict__ loc,
                              const float* __restrict__ Ww1) {
    int t = threadIdx.x;
    int row0 = blockIdx.x * 16;
    int col = t & 127;
    int rh = t >> 7;                   // 0 or 1

    if (blockIdx.x == 0 && t < 256) {  // zero layer-2 stat accumulators
        g_sum2[t] = 0.f; g_sum2[t + 256] = 0.f;
        g_sq2[t] = 0.f;  g_sq2[t + 256] = 0.f;
    }

    float s = 0.f, q = 0.f;
    #pragma unroll
    for (int r = 0; r < 16; r += 2) {
        int idx = (row0 + r + rh) * H1_D + col;
        float v = 0.f;
        #pragma unroll
        for (int k = 0; k < NSPLIT; k++) v += g_h1p[idx + k * SPLIT_OFF];
        g_h1[idx] = v;
        s += v; q += v * v;
    }
    atomicAdd(&g_sum1[col], s); atomicAdd(&g_sq1[col], q);

    // where path: recompute h1w = loc @ Ww1 (rank-2)
    float w0 = Ww1[col], w1 = Ww1[H1_D + col];
    s = 0.f; q = 0.f;
    #pragma unroll
    for (int r = 0; r < 16; r += 2) {
        int b = row0 + r + rh;
        float v = loc[2 * b] * w0 + loc[2 * b + 1] * w1;
        s += v; q += v * v;
    }
    atomicAdd(&g_sum1[H1_D + col], s); atomicAdd(&g_sq1[H1_D + col], q);
}

// ---------------- K4: GEMM2 (both paths); BN inline; stats2 fused ------------
__global__ void gemm2_kernel(const float* __restrict__ W2,     // (128,256)
                             const float* __restrict__ Ww2,    // (128,256)
                             const float* __restrict__ loc,
                             const float* __restrict__ Ww1,    // (2,128)
                             const float* __restrict__ g1, const float* __restrict__ be1,
                             const float* __restrict__ gw1, const float* __restrict__ bew1) {
    __shared__ float As[16][68];
    __shared__ float Bs[16][68];
    __shared__ float2 red[16][64];
    int path = blockIdx.z;
    const float* W   = path ? Ww2   : W2;
    float*       out = path ? g_h2w : g_h2;
    const float* gam = path ? gw1 : g1;
    const float* bet = path ? bew1 : be1;
    int soff = path * H1_D;

    int t = threadIdx.x;
    int rowBase = blockIdx.x * 64;
    int colBase = blockIdx.y * 64;
    int ty = t >> 4, tx = t & 15;
    float acc[4][4] = {};

    int lc = t & 15;
    int lr = (t >> 4) << 2;
    int bc = t & 63;
    int br = t >> 6;

    float lxv[4], lyv[4];
    if (path) {
        #pragma unroll
        for (int rr = 0; rr < 4; rr++) {
            int row = rowBase + lr + rr;
            lxv[rr] = loc[2 * row];
            lyv[rr] = loc[2 * row + 1];
        }
    }

    for (int k0 = 0; k0 < H1_D; k0 += 16) {
        int kc = k0 + lc;
        float mean = g_sum1[soff + kc] * (1.0f / 4096.0f);
        float var  = g_sq1[soff + kc] * (1.0f / 4096.0f) - mean * mean;
        float s = gam[kc] * rsqrtf(var + EPS);
        float h = bet[kc] - mean * s;
        if (path == 0) {
            #pragma unroll
            for (int rr = 0; rr < 4; rr++) {
                float v = g_h1[(size_t)(rowBase + lr + rr) * H1_D + kc];
                As[lc][lr + rr] = fmaxf(v * s + h, 0.f);
            }
        } else {
            float w0 = Ww1[kc], w1 = Ww1[H1_D + kc];
            #pragma unroll
            for (int rr = 0; rr < 4; rr++) {
                float v = lxv[rr] * w0 + lyv[rr] * w1;
                As[lc][lr + rr] = fmaxf(v * s + h, 0.f);
            }
        }
        #pragma unroll
        for (int pp = 0; pp < 4; pp++)
            Bs[br * 4 + pp][bc] = W[(size_t)(k0 + br * 4 + pp) * H2_D + colBase + bc];
        __syncthreads();
        #pragma unroll
        for (int kk = 0; kk < 16; kk++) {
            float4 a = *(const float4*)&As[kk][ty * 4];
            float4 b = *(const float4*)&Bs[kk][tx * 4];
            acc[0][0] += a.x * b.x; acc[0][1] += a.x * b.y; acc[0][2] += a.x * b.z; acc[0][3] += a.x * b.w;
            acc[1][0] += a.y * b.x; acc[1][1] += a.y * b.y; acc[1][2] += a.y * b.z; acc[1][3] += a.y * b.w;
            acc[2][0] += a.z * b.x; acc[2][1] += a.z * b.y; acc[2][2] += a.z * b.z; acc[2][3] += a.z * b.w;
            acc[3][0] += a.w * b.x; acc[3][1] += a.w * b.y; acc[3][2] += a.w * b.z; acc[3][3] += a.w * b.w;
        }
        __syncthreads();
    }
    #pragma unroll
    for (int rr = 0; rr < 4; rr++) {
        int row = rowBase + ty * 4 + rr;
        #pragma unroll
        for (int cc = 0; cc < 4; cc++)
            out[(size_t)row * H2_D + colBase + tx * 4 + cc] = acc[rr][cc];
    }

    // fused column stats over this block's 64 rows
    #pragma unroll
    for (int cc = 0; cc < 4; cc++) {
        float s = acc[0][cc] + acc[1][cc] + acc[2][cc] + acc[3][cc];
        float q = acc[0][cc] * acc[0][cc] + acc[1][cc] * acc[1][cc]
                + acc[2][cc] * acc[2][cc] + acc[3][cc] * acc[3][cc];
        red[ty][tx * 4 + cc] = make_float2(s, q);
    }
    __syncthreads();
    if (t < 64) {
        float s = 0.f, q = 0.f;
        #pragma unroll
        for (int i = 0; i < 16; i++) {
            float2 v = red[i][t];
            s += v.x; q += v.y;
        }
        int col = path * H2_D + colBase + t;
        atomicAdd(&g_sum2[col], s);
        atomicAdd(&g_sq2[col], q);
    }
}

// ---------------- K6: out = relu(BN(h2) + BN(h2w)), finalize inline ----------
__global__ void final_kernel(const float* __restrict__ g2, const float* __restrict__ be2,
                             const float* __restrict__ gw2, const float* __restrict__ bew2,
                             float* __restrict__ out) {
    int idx = blockIdx.x * blockDim.x + threadIdx.x;   // 1048576
    int c = idx & 255;
    float m0 = g_sum2[c] * (1.0f / 4096.0f);
    float v0 = g_sq2[c] * (1.0f / 4096.0f) - m0 * m0;
    float s0 = g2[c] * rsqrtf(v0 + EPS);
    float h0 = be2[c] - m0 * s0;
    float m1 = g_sum2[256 + c] * (1.0f / 4096.0f);
    float v1 = g_sq2[256 + c] * (1.0f / 4096.0f) - m1 * m1;
    float s1 = gw2[c] * rsqrtf(v1 + EPS);
    float h1 = bew2[c] - m1 * s1;
    float a = g_h2[idx]  * s0 + h0;
    float b = g_h2w[idx] * s1 + h1;
    out[idx] = fmaxf(a + b, 0.f);
}

// ---------------- launch -----------------------------------------------------
extern "C" void kernel_launch(void* const* d_in, const int* in_sizes, int n_in,
                              void* d_out, int out_size) {
    const float* x        = (const float*)d_in[0];
    const float* loc      = (const float*)d_in[1];
    const float* what_W1  = (const float*)d_in[2];
    const float* what_g1  = (const float*)d_in[4];
    const float* what_be1 = (const float*)d_in[5];
    const float* what_W2  = (const float*)d_in[6];
    const float* what_g2  = (const float*)d_in[8];
    const float* what_be2 = (const float*)d_in[9];
    const float* where_W1  = (const float*)d_in[10];
    const float* where_g1  = (const float*)d_in[12];
    const float* where_be1 = (const float*)d_in[13];
    const float* where_W2  = (const float*)d_in[14];
    const float* where_g2  = (const float*)d_in[16];
    const float* where_be2 = (const float*)d_in[17];
    float* out = (float*)d_out;

    const int FOV_SMEM = (WIN * WSTRIDE + 56 * L1W + 28 * L2W) * sizeof(float); // ~66.6KB
    static float* p_phi = nullptr;
    if (!p_phi) {
        cudaGetSymbolAddress((void**)&p_phi, g_phi);
        cudaFuncSetAttribute(foveate_kernel,
                             cudaFuncAttributeMaxDynamicSharedMemorySize, FOV_SMEM);
    }

    foveate_kernel<<<B_SZ, 512, FOV_SMEM>>>(x, loc, p_phi);
    gemm1_kernel<<<dim3(B_SZ / 64, H1_D / 64, NSPLIT), 256>>>(p_phi, what_W1);
    stats1_kernel<<<256, 256>>>(loc, where_W1);
    gemm2_kernel<<<dim3(B_SZ / 64, H2_D / 64, 2), 256>>>(
        what_W2, where_W2, loc, where_W1,
        what_g1, what_be1, where_g1, where_be1);
    final_kernel<<<(B_SZ * H2_D) / 512, 512>>>(
        what_g2, what_be2, where_g2, where_be2, out);
}

// round 7
// speedup vs baseline: 1.6487x; 1.0637x over previous
#include <cuda_runtime.h>
#include <cuda_bf16.h>

// Problem constants
#define B_SZ   4096
#define HH     128
#define PHI_D  784
#define H1_D   128
#define H2_D   256
#define L1W    57
#define L2W    29
#define EPS    1e-5f
#define NSPLIT 8
#define SPLIT_OFF (B_SZ * H1_D)

// ---------------- scratch ----------------------------------------------------
__device__ float g_phi[B_SZ * PHI_D];
__device__ float g_h1p[NSPLIT * B_SZ * H1_D];
__device__ float g_h1 [B_SZ * H1_D];
__device__ float g_h2 [B_SZ * H2_D];
__device__ float g_h2w[B_SZ * H2_D];
__device__ float g_sum1[2 * H1_D];
__device__ float g_sq1 [2 * H1_D];
__device__ float g_sum2[2 * H2_D];
__device__ float g_sq2 [2 * H2_D];

// ---------------- K1: foveate via pyramid, low-smem --------------------------
// Patch p: size 14*2^p, window top-left 56-7*2^p: p0->49, p1->42, p2->28, p3->0
__global__ __launch_bounds__(512) void foveate_kernel(const float* __restrict__ x,
                                                      const float* __restrict__ loc) {
    __shared__ float L1[56 * L1W];   // 2x2 sums of window
    __shared__ float L2[28 * L2W];   // 4x4 sums
    __shared__ float ctr[14 * 15];   // patch0 pixels (window offset 49)

    int b = blockIdx.x;
    if (b == 0 && threadIdx.x < 256) {          // zero layer-1 stat accumulators
        g_sum1[threadIdx.x] = 0.f;
        g_sq1[threadIdx.x] = 0.f;
    }
    float lx = loc[2 * b + 0];
    float ly = loc[2 * b + 1];
    int cx = (int)(0.5f * ((lx + 1.0f) * 128.0f));
    int cy = (int)(0.5f * ((ly + 1.0f) * 128.0f));
    int wy0 = cy - 56, wx0 = cx - 56;
    const float* xb = x + (size_t)b * HH * HH;

    auto ld = [&](int gy, int gx) -> float {
        return (gy >= 0 && gy < HH && gx >= 0 && gx < HH) ? xb[gy * HH + gx] : 0.f;
    };

    // L1 directly from global: each window pixel read exactly once
    for (int i = threadIdx.x; i < 56 * 56; i += 512) {
        int r = i / 56, c = i - r * 56;
        int gy = wy0 + 2 * r, gx = wx0 + 2 * c;
        L1[r * L1W + c] = (ld(gy, gx) + ld(gy, gx + 1))
                        + (ld(gy + 1, gx) + ld(gy + 1, gx + 1));
    }
    // center 14x14 (patch0) raw pixels
    if (threadIdx.x < 196) {
        int i = threadIdx.x / 14, j = threadIdx.x - i * 14;
        ctr[i * 15 + j] = ld(wy0 + 49 + i, wx0 + 49 + j);
    }
    __syncthreads();

    for (int i = threadIdx.x; i < 28 * 28; i += 512) {
        int r = i / 28, c = i - r * 28;
        const float* a0 = &L1[(2 * r) * L1W + 2 * c];
        const float* a1 = a0 + L1W;
        L2[r * L2W + c] = (a0[0] + a0[1]) + (a1[0] + a1[1]);
    }
    __syncthreads();

    for (int o = threadIdx.x; o < PHI_D; o += 512) {
        int p   = o / 196;
        int rem = o - p * 196;
        int i   = rem / 14;
        int j   = rem - i * 14;
        float v;
        if (p == 0) {
            v = ctr[i * 15 + j];
        } else if (p == 1) {
            v = L1[(21 + i) * L1W + 21 + j] * 0.25f;
        } else if (p == 2) {
            v = L2[(7 + i) * L2W + 7 + j] * 0.0625f;
        } else {
            const float* q0 = &L2[(2 * i) * L2W + 2 * j];
            const float* q1 = q0 + L2W;
            v = ((q0[0] + q0[1]) + (q1[0] + q1[1])) * (1.0f / 64.0f);
        }
        g_phi[(size_t)b * PHI_D + o] = v;
    }
}

// ---------------- K2: GEMM1 split-K, BM=64 BN=128 BK=16, micro 4x8, db -------
__global__ __launch_bounds__(256) void gemm1_kernel(const float* __restrict__ W) {
    __shared__ float As[2][16][68];
    __shared__ float Bs[2][16][132];
    int s = blockIdx.y;
    int t0 = (s == 0) ? 0 : 7 + 6 * (s - 1);    // 49 tiles: [7,6,6,6,6,6,6,6]
    int nt = (s == 0) ? 7 : 6;
    float* out = g_h1p + (size_t)s * SPLIT_OFF;

    int t = threadIdx.x;
    int rowBase = blockIdx.x * 64;
    int tx = t & 15, ty = t >> 4;
    int lc = t & 15, lr = (t >> 4) << 2;
    int bc = (t & 31) << 2, brr = (t >> 5) << 1;
    float acc[4][8] = {};
    float ar[4]; float4 b0r, b1r;

    // prologue
    {
        int k0 = t0 * 16;
        #pragma unroll
        for (int rr = 0; rr < 4; rr++)
            ar[rr] = g_phi[(size_t)(rowBase + lr + rr) * PHI_D + k0 + lc];
        b0r = *(const float4*)&W[(size_t)(k0 + brr) * H1_D + bc];
        b1r = *(const float4*)&W[(size_t)(k0 + brr + 1) * H1_D + bc];
        #pragma unroll
        for (int rr = 0; rr < 4; rr++) As[0][lc][lr + rr] = ar[rr];
        *(float4*)&Bs[0][brr][bc] = b0r;
        *(float4*)&Bs[0][brr + 1][bc] = b1r;
    }
    __syncthreads();
    int cur = 0;
    for (int i = 0; i < nt; i++) {
        if (i + 1 < nt) {
            int k0 = (t0 + i + 1) * 16;
            #pragma unroll
            for (int rr = 0; rr < 4; rr++)
                ar[rr] = g_phi[(size_t)(rowBase + lr + rr) * PHI_D + k0 + lc];
            b0r = *(const float4*)&W[(size_t)(k0 + brr) * H1_D + bc];
            b1r = *(const float4*)&W[(size_t)(k0 + brr + 1) * H1_D + bc];
        }
        #pragma unroll
        for (int kk = 0; kk < 16; kk++) {
            float4 a  = *(const float4*)&As[cur][kk][ty * 4];
            float4 b0 = *(const float4*)&Bs[cur][kk][tx * 8];
            float4 b1 = *(const float4*)&Bs[cur][kk][tx * 8 + 4];
            float av[4] = {a.x, a.y, a.z, a.w};
            float bv[8] = {b0.x, b0.y, b0.z, b0.w, b1.x, b1.y, b1.z, b1.w};
            #pragma unroll
            for (int rr = 0; rr < 4; rr++)
                #pragma unroll
                for (int cc = 0; cc < 8; cc++)
                    acc[rr][cc] += av[rr] * bv[cc];
        }
        if (i + 1 < nt) {
            int nxt = cur ^ 1;
            #pragma unroll
            for (int rr = 0; rr < 4; rr++) As[nxt][lc][lr + rr] = ar[rr];
            *(float4*)&Bs[nxt][brr][bc] = b0r;
            *(float4*)&Bs[nxt][brr + 1][bc] = b1r;
            __syncthreads();
            cur = nxt;
        }
    }
    #pragma unroll
    for (int rr = 0; rr < 4; rr++) {
        int row = rowBase + ty * 4 + rr;
        *(float4*)&out[(size_t)row * H1_D + tx * 8] =
            make_float4(acc[rr][0], acc[rr][1], acc[rr][2], acc[rr][3]);
        *(float4*)&out[(size_t)row * H1_D + tx * 8 + 4] =
            make_float4(acc[rr][4], acc[rr][5], acc[rr][6], acc[rr][7]);
    }
}

// ---------------- K3: reduce partials -> g_h1 + column stats (both paths) ----
__global__ void stats1_kernel(const float* __restrict__ loc,
                              const float* __restrict__ Ww1) {
    int t = threadIdx.x;
    int row0 = blockIdx.x * 16;
    int col = t & 127;
    int rh = t >> 7;

    if (blockIdx.x == 0 && t < 256) {  // zero layer-2 stat accumulators
        g_sum2[t] = 0.f; g_sum2[t + 256] = 0.f;
        g_sq2[t] = 0.f;  g_sq2[t + 256] = 0.f;
    }

    float s = 0.f, q = 0.f;
    #pragma unroll
    for (int r = 0; r < 16; r += 2) {
        int idx = (row0 + r + rh) * H1_D + col;
        float v = 0.f;
        #pragma unroll
        for (int k = 0; k < NSPLIT; k++) v += g_h1p[idx + k * SPLIT_OFF];
        g_h1[idx] = v;
        s += v; q += v * v;
    }
    atomicAdd(&g_sum1[col], s); atomicAdd(&g_sq1[col], q);

    float w0 = Ww1[col], w1 = Ww1[H1_D + col];
    s = 0.f; q = 0.f;
    #pragma unroll
    for (int r = 0; r < 16; r += 2) {
        int b = row0 + r + rh;
        float v = loc[2 * b] * w0 + loc[2 * b + 1] * w1;
        s += v; q += v * v;
    }
    atomicAdd(&g_sum1[H1_D + col], s); atomicAdd(&g_sq1[H1_D + col], q);
}

// ---------------- K4: GEMM2 BM=64 BN=128 micro 4x8 db; BN inline; stats fused
__global__ __launch_bounds__(256) void gemm2_kernel(
        const float* __restrict__ W2,     // (128,256)
        const float* __restrict__ Ww2,    // (128,256)
        const float* __restrict__ loc,
        const float* __restrict__ Ww1,    // (2,128)
        const float* __restrict__ g1, const float* __restrict__ be1,
        const float* __restrict__ gw1, const float* __restrict__ bew1) {
    __shared__ float As[2][16][68];
    __shared__ float Bs[2][16][132];
    __shared__ float2 red[16][129];
    int path = blockIdx.z;
    const float* W   = path ? Ww2  : W2;
    float*       out = path ? g_h2w : g_h2;
    const float* gam = path ? gw1 : g1;
    const float* bet = path ? bew1 : be1;
    int soff = path * H1_D;

    int t = threadIdx.x;
    int rowBase = blockIdx.x * 64;
    int colBase = blockIdx.y * 128;
    int tx = t & 15, ty = t >> 4;
    int lc = t & 15, lr = (t >> 4) << 2;
    int bc = (t & 31) << 2, brr = (t >> 5) << 1;
    float acc[4][8] = {};
    float ar[4]; float4 b0r, b1r;

    float lxv[4], lyv[4];
    if (path) {
        #pragma unroll
        for (int rr = 0; rr < 4; rr++) {
            int row = rowBase + lr + rr;
            lxv[rr] = loc[2 * row];
            lyv[rr] = loc[2 * row + 1];
        }
    }

    // A store with BN+relu for K-tile kt into buffer buf
    auto storeA = [&](int kt, int buf) {
        int kc = kt * 16 + lc;
        float mean = g_sum1[soff + kc] * (1.0f / 4096.0f);
        float var  = g_sq1[soff + kc] * (1.0f / 4096.0f) - mean * mean;
        float sc = gam[kc] * rsqrtf(var + EPS);
        float sh = bet[kc] - mean * sc;
        if (path == 0) {
            #pragma unroll
            for (int rr = 0; rr < 4; rr++)
                As[buf][lc][lr + rr] = fmaxf(ar[rr] * sc + sh, 0.f);
        } else {
            float w0 = Ww1[kc], w1 = Ww1[H1_D + kc];
            #pragma unroll
            for (int rr = 0; rr < 4; rr++)
                As[buf][lc][lr + rr] = fmaxf((lxv[rr] * w0 + lyv[rr] * w1) * sc + sh, 0.f);
        }
    };
    auto loadT = [&](int kt) {
        int k0 = kt * 16;
        if (path == 0) {
            #pragma unroll
            for (int rr = 0; rr < 4; rr++)
                ar[rr] = g_h1[(size_t)(rowBase + lr + rr) * H1_D + k0 + lc];
        }
        b0r = *(const float4*)&W[(size_t)(k0 + brr) * H2_D + colBase + bc];
        b1r = *(const float4*)&W[(size_t)(k0 + brr + 1) * H2_D + colBase + bc];
    };

    loadT(0);
    storeA(0, 0);
    *(float4*)&Bs[0][brr][bc] = b0r;
    *(float4*)&Bs[0][brr + 1][bc] = b1r;
    __syncthreads();
    int cur = 0;
    const int NT = H1_D / 16;   // 8
    for (int i = 0; i < NT; i++) {
        if (i + 1 < NT) loadT(i + 1);
        #pragma unroll
        for (int kk = 0; kk < 16; kk++) {
            float4 a  = *(const float4*)&As[cur][kk][ty * 4];
            float4 b0 = *(const float4*)&Bs[cur][kk][tx * 8];
            float4 b1 = *(const float4*)&Bs[cur][kk][tx * 8 + 4];
            float av[4] = {a.x, a.y, a.z, a.w};
            float bv[8] = {b0.x, b0.y, b0.z, b0.w, b1.x, b1.y, b1.z, b1.w};
            #pragma unroll
            for (int rr = 0; rr < 4; rr++)
                #pragma unroll
                for (int cc = 0; cc < 8; cc++)
                    acc[rr][cc] += av[rr] * bv[cc];
        }
        if (i + 1 < NT) {
            int nxt = cur ^ 1;
            storeA(i + 1, nxt);
            *(float4*)&Bs[nxt][brr][bc] = b0r;
            *(float4*)&Bs[nxt][brr + 1][bc] = b1r;
            __syncthreads();
            cur = nxt;
        }
    }
    #pragma unroll
    for (int rr = 0; rr < 4; rr++) {
        int row = rowBase + ty * 4 + rr;
        *(float4*)&out[(size_t)row * H2_D + colBase + tx * 8] =
            make_float4(acc[rr][0], acc[rr][1], acc[rr][2], acc[rr][3]);
        *(float4*)&out[(size_t)row * H2_D + colBase + tx * 8 + 4] =
            make_float4(acc[rr][4], acc[rr][5], acc[rr][6], acc[rr][7]);
    }

    // fused column stats over this block's 64 rows (128 cols)
    __syncthreads();
    #pragma unroll
    for (int cc = 0; cc < 8; cc++) {
        float s = acc[0][cc] + acc[1][cc] + acc[2][cc] + acc[3][cc];
        float q = acc[0][cc] * acc[0][cc] + acc[1][cc] * acc[1][cc]
                + acc[2][cc] * acc[2][cc] + acc[3][cc] * acc[3][cc];
        red[ty][tx * 8 + cc] = make_float2(s, q);
    }
    __syncthreads();
    if (t < 128) {
        float s = 0.f, q = 0.f;
        #pragma unroll
        for (int i = 0; i < 16; i++) {
            float2 v = red[i][t];
            s += v.x; q += v.y;
        }
        int col = path * H2_D + colBase + t;
        atomicAdd(&g_sum2[col], s);
        atomicAdd(&g_sq2[col], q);
    }
}

// ---------------- K6: out = relu(BN(h2) + BN(h2w)), finalize inline ----------
__global__ void final_kernel(const float* __restrict__ g2, const float* __restrict__ be2,
                             const float* __restrict__ gw2, const float* __restrict__ bew2,
                             float* __restrict__ out) {
    int idx = blockIdx.x * blockDim.x + threadIdx.x;
    int c = idx & 255;
    float m0 = g_sum2[c] * (1.0f / 4096.0f);
    float v0 = g_sq2[c] * (1.0f / 4096.0f) - m0 * m0;
    float s0 = g2[c] * rsqrtf(v0 + EPS);
    float h0 = be2[c] - m0 * s0;
    float m1 = g_sum2[256 + c] * (1.0f / 4096.0f);
    float v1 = g_sq2[256 + c] * (1.0f / 4096.0f) - m1 * m1;
    float s1 = gw2[c] * rsqrtf(v1 + EPS);
    float h1 = bew2[c] - m1 * s1;
    float a = g_h2[idx]  * s0 + h0;
    float b = g_h2w[idx] * s1 + h1;
    out[idx] = fmaxf(a + b, 0.f);
}

// ---------------- launch -----------------------------------------------------
extern "C" void kernel_launch(void* const* d_in, const int* in_sizes, int n_in,
                              void* d_out, int out_size) {
    const float* x        = (const float*)d_in[0];
    const float* loc      = (const float*)d_in[1];
    const float* what_W1  = (const float*)d_in[2];
    const float* what_g1  = (const float*)d_in[4];
    const float* what_be1 = (const float*)d_in[5];
    const float* what_W2  = (const float*)d_in[6];
    const float* what_g2  = (const float*)d_in[8];
    const float* what_be2 = (const float*)d_in[9];
    const float* where_W1  = (const float*)d_in[10];
    const float* where_g1  = (const float*)d_in[12];
    const float* where_be1 = (const float*)d_in[13];
    const float* where_W2  = (const float*)d_in[14];
    const float* where_g2  = (const float*)d_in[16];
    const float* where_be2 = (const float*)d_in[17];
    float* out = (float*)d_out;

    foveate_kernel<<<B_SZ, 512>>>(x, loc);
    gemm1_kernel<<<dim3(B_SZ / 64, NSPLIT), 256>>>(what_W1);
    stats1_kernel<<<256, 256>>>(loc, where_W1);
    gemm2_kernel<<<dim3(B_SZ / 64, 2, 2), 256>>>(
        what_W2, where_W2, loc, where_W1,
        what_g1, what_be1, where_g1, where_be1);
    final_kernel<<<(B_SZ * H2_D) / 512, 512>>>(
        what_g2, what_be2, where_g2, where_be2, out);
}